// round 15
// baseline (speedup 1.0000x reference)
#include <cuda_runtime.h>
#include <cuda_fp16.h>
#include <cstdint>

// Problem constants (fixed by the dataset)
#define NN 100000
#define NE 1600000
#define DD 64
#define CAP 64          // bucket capacity per node (Poisson(16): P(deg>64)~2e-22)

#define XS_STRIDE 72    // halves; 144B rows: 16B-aligned + conflict-free ldmatrix

// ---------------- device scratch (no allocations allowed) ----------------
// g_cnt relies on BSS zero-init; agg layer-2 re-zeroes it (replay invariant).
__device__ __align__(256) int     g_cnt[NN];
__device__ __align__(256) int     g_bkt[(size_t)NN * CAP];   // bucket CSR
__device__ __align__(256) __half2 g_hn[(size_t)NN * 32];     // (x@W)*dinv, fp16
__device__ __align__(256) __half  g_h1h[(size_t)NN * DD];    // layer-1 out, fp16

// ------------- standalone bucket scatter: 4 edges/thread via int4 -----------
__global__ void k_scatter(const int* __restrict__ src,
                          const int* __restrict__ dst, int e4, int n) {
    int i = blockIdx.x * blockDim.x + threadIdx.x;
    if (i >= e4) return;
    int4 s4 = reinterpret_cast<const int4*>(src)[i];
    int4 d4 = reinterpret_cast<const int4*>(dst)[i];
    int dd[4] = {d4.x, d4.y, d4.z, d4.w};
    int ss[4] = {s4.x, s4.y, s4.z, s4.w};
#pragma unroll
    for (int q = 0; q < 4; q++) {
        if ((unsigned)dd[q] >= (unsigned)n || (unsigned)ss[q] >= (unsigned)n) continue;
        int slot = atomicAdd(&g_cnt[dd[q]], 1);
        if (slot < CAP) g_bkt[(size_t)dd[q] * CAP + slot] = ss[q];
    }
}

// -------- GEMM: g_hn[row] = fp16((x@W) * rsqrt(cnt[row]+1)) -----------------
// 128 rows/block, 256 threads/8 warps (16 rows/warp, one m16 tile) -> smaller
// serial chain per block, 782 blocks, 3 blocks/SM (was 2) for latency hiding.
__global__ void __launch_bounds__(256) k_gemm(
    const float* __restrict__ emb, const float* __restrict__ W,
    int layer, int n) {
    __shared__ __half xs[128 * XS_STRIDE];       // 18432 B
    __shared__ __half wt[64 * XS_STRIDE];        //  9216 B  (wt[n][k])
    int tid = threadIdx.x;
    int base = blockIdx.x * 128;

    // ---- stage x rows -> fp16 shared (all 256 threads cooperate) ----
    if (layer == 0) {
#pragma unroll
        for (int ii = 0; ii < 8; ii++) {
            int i = tid + 256 * ii;              // 0..2047 (128 rows x 16 f4)
            int r = i >> 4, kk = i & 15;
            int gr = base + r;
            float4 q = (gr < n)
                ? reinterpret_cast<const float4*>(emb)[(size_t)gr * 16 + kk]
                : make_float4(0.f, 0.f, 0.f, 0.f);
            __half2* dp = reinterpret_cast<__half2*>(&xs[r * XS_STRIDE + kk * 4]);
            dp[0] = __floats2half2_rn(q.x, q.y);
            dp[1] = __floats2half2_rn(q.z, q.w);
        }
    } else {
#pragma unroll
        for (int ii = 0; ii < 4; ii++) {
            int i = tid + 256 * ii;              // 0..1023 (128 rows x 8 u4)
            int r = i >> 3, pc = i & 7;
            int gr = base + r;
            uint4 v = (gr < n)
                ? reinterpret_cast<const uint4*>(g_h1h)[(size_t)gr * 8 + pc]
                : make_uint4(0, 0, 0, 0);
            reinterpret_cast<uint4*>(&xs[r * XS_STRIDE])[pc] = v;
        }
    }
    // ---- stage W -> fp16 transposed shared (wt[n][k]) ----
    {
        const float4* Wp4 = reinterpret_cast<const float4*>(W);
#pragma unroll
        for (int ii = 0; ii < 4; ii++) {
            int i4 = tid + 256 * ii;             // 1024 float4 total
            float4 wv = Wp4[i4];
            int flat = i4 * 4;
            int k = flat >> 6;
            int nn = flat & 63;
            wt[(nn)     * XS_STRIDE + k] = __float2half_rn(wv.x);
            wt[(nn + 1) * XS_STRIDE + k] = __float2half_rn(wv.y);
            wt[(nn + 2) * XS_STRIDE + k] = __float2half_rn(wv.z);
            wt[(nn + 3) * XS_STRIDE + k] = __float2half_rn(wv.w);
        }
    }
    __syncthreads();

    int wid = tid >> 5, lane = tid & 31;
    int g = lane >> 2, t = lane & 3;
    uint32_t xs_u32 = (uint32_t)__cvta_generic_to_shared(xs);

    // A fragments via ldmatrix.x4 (one m16 tile per warp)
    uint32_t afr[4][4];
    {
        int rsh = wid * 16 + (lane & 15);
#pragma unroll
        for (int kc = 0; kc < 4; kc++) {
            uint32_t addr = xs_u32 + rsh * (XS_STRIDE * 2) + kc * 32 + (lane >> 4) * 16;
            asm volatile("ldmatrix.sync.aligned.m8n8.x4.shared.b16 {%0,%1,%2,%3}, [%4];"
                         : "=r"(afr[kc][0]), "=r"(afr[kc][1]),
                           "=r"(afr[kc][2]), "=r"(afr[kc][3])
                         : "r"(addr));
        }
    }

    float c[8][4];
#pragma unroll
    for (int nt = 0; nt < 8; nt++)
#pragma unroll
        for (int q = 0; q < 4; q++) c[nt][q] = 0.f;

#pragma unroll
    for (int nt = 0; nt < 8; nt++) {
        uint32_t b0[4], b1[4];
        int nrow = nt * 8 + g;
#pragma unroll
        for (int kc = 0; kc < 4; kc++) {
            b0[kc] = *reinterpret_cast<const uint32_t*>(&wt[nrow * XS_STRIDE + kc * 16 + 2 * t]);
            b1[kc] = *reinterpret_cast<const uint32_t*>(&wt[nrow * XS_STRIDE + kc * 16 + 8 + 2 * t]);
        }
#pragma unroll
        for (int kc = 0; kc < 4; kc++) {
            asm volatile(
                "mma.sync.aligned.m16n8k16.row.col.f32.f16.f16.f32 "
                "{%0,%1,%2,%3}, {%4,%5,%6,%7}, {%8,%9}, {%0,%1,%2,%3};"
                : "+f"(c[nt][0]), "+f"(c[nt][1]), "+f"(c[nt][2]), "+f"(c[nt][3])
                : "r"(afr[kc][0]), "r"(afr[kc][1]),
                  "r"(afr[kc][2]), "r"(afr[kc][3]),
                  "r"(b0[kc]), "r"(b1[kc]));
        }
    }
    __syncthreads();   // xs reuse

    // ---- epilogue: scale by dinv, frags -> shared (conflict-free) ----
    {
        int rl = wid * 16 + g;
        int r0 = base + rl, r1 = r0 + 8;
        float di0 = (r0 < n) ? rsqrtf((float)(g_cnt[r0] + 1)) : 0.f;
        float di1 = (r1 < n) ? rsqrtf((float)(g_cnt[r1] + 1)) : 0.f;
#pragma unroll
        for (int nt = 0; nt < 8; nt++) {
            int col = nt * 8 + 2 * t;
            *reinterpret_cast<__half2*>(&xs[rl * XS_STRIDE + col]) =
                __floats2half2_rn(c[nt][0] * di0, c[nt][1] * di0);
            *reinterpret_cast<__half2*>(&xs[(rl + 8) * XS_STRIDE + col]) =
                __floats2half2_rn(c[nt][2] * di1, c[nt][3] * di1);
        }
    }
    __syncthreads();

    // ---- shared -> global, fully coalesced STG.128 ----
    uint4* outp = reinterpret_cast<uint4*>(g_hn) + (size_t)base * 8;
    int limit = (min(128, n - base)) * 8;
#pragma unroll
    for (int ii = 0; ii < 4; ii++) {
        int i = tid + 256 * ii;
        if (i < limit) {
            int r = i >> 3, pc = i & 7;
            outp[i] = reinterpret_cast<uint4*>(&xs[r * XS_STRIDE])[pc];
        }
    }
}

// ---- aggregation: out = relu(dinv_d*(hn_d + sum_s hn_s) + b) ---------------
// 8 lanes/node (4 nodes/warp). 8-wide fp16 HADD2 tree per iteration (8 gathers
// in flight, 28 HADD2 + one fp32 drain per 8 edges). Mean deg=16 -> most nodes
// run exactly two clean iterations.
__global__ void __launch_bounds__(256) k_agg(
    const float* __restrict__ b, float* __restrict__ dout,
    int layer, int n) {
    int tid = blockIdx.x * blockDim.x + threadIdx.x;
    int node = tid >> 3;
    int sub = tid & 7;                 // owns half2[4*sub .. 4*sub+3]
    if (node >= n) return;
    const uint4* hn4 = reinterpret_cast<const uint4*>(g_hn);

    int cnt = g_cnt[node];
    float di = rsqrtf((float)(cnt + 1));
    int len = min(cnt, CAP);
    const int4* bp = reinterpret_cast<const int4*>(g_bkt) + (unsigned)(node * (CAP / 4));

    uint4 uself = hn4[(unsigned)(node * 8 + sub)];
    float2 a0 = __half22float2(*reinterpret_cast<__half2*>(&uself.x));
    float2 a1 = __half22float2(*reinterpret_cast<__half2*>(&uself.y));
    float2 a2 = __half22float2(*reinterpret_cast<__half2*>(&uself.z));
    float2 a3 = __half22float2(*reinterpret_cast<__half2*>(&uself.w));

#define H2(v) (*reinterpret_cast<const __half2*>(&(v)))
#define TREE8(C, ACC)                                                       \
    {                                                                       \
        __half2 s0 = __hadd2(H2(u0.C), H2(u1.C));                           \
        __half2 s1 = __hadd2(H2(u2.C), H2(u3.C));                           \
        __half2 s2 = __hadd2(H2(u4.C), H2(u5.C));                           \
        __half2 s3 = __hadd2(H2(u6.C), H2(u7.C));                           \
        float2 f = __half22float2(__hadd2(__hadd2(s0, s1), __hadd2(s2, s3)));\
        ACC.x += f.x; ACC.y += f.y;                                         \
    }
#define TREE4(C, ACC)                                                       \
    {                                                                       \
        __half2 s0 = __hadd2(H2(u0.C), H2(u1.C));                           \
        __half2 s1 = __hadd2(H2(u2.C), H2(u3.C));                           \
        float2 f = __half22float2(__hadd2(s0, s1));                         \
        ACC.x += f.x; ACC.y += f.y;                                         \
    }

    int p = 0;
    for (; p + 8 <= len; p += 8) {
        int4 e0 = bp[p >> 2];                     // broadcast across 8 lanes
        int4 e1 = bp[(p >> 2) + 1];
        uint4 u0 = hn4[(unsigned)(e0.x * 8 + sub)];
        uint4 u1 = hn4[(unsigned)(e0.y * 8 + sub)];
        uint4 u2 = hn4[(unsigned)(e0.z * 8 + sub)];
        uint4 u3 = hn4[(unsigned)(e0.w * 8 + sub)];
        uint4 u4 = hn4[(unsigned)(e1.x * 8 + sub)];
        uint4 u5 = hn4[(unsigned)(e1.y * 8 + sub)];
        uint4 u6 = hn4[(unsigned)(e1.z * 8 + sub)];
        uint4 u7 = hn4[(unsigned)(e1.w * 8 + sub)];
        TREE8(x, a0) TREE8(y, a1) TREE8(z, a2) TREE8(w, a3)
    }
    if (p + 4 <= len) {
        int4 e0 = bp[p >> 2];
        uint4 u0 = hn4[(unsigned)(e0.x * 8 + sub)];
        uint4 u1 = hn4[(unsigned)(e0.y * 8 + sub)];
        uint4 u2 = hn4[(unsigned)(e0.z * 8 + sub)];
        uint4 u3 = hn4[(unsigned)(e0.w * 8 + sub)];
        TREE4(x, a0) TREE4(y, a1) TREE4(z, a2) TREE4(w, a3)
        p += 4;
    }
    for (; p < len; p++) {
        int s = g_bkt[(unsigned)(node * CAP + p)];
        uint4 u0 = hn4[(unsigned)(s * 8 + sub)];
        float2 f0 = __half22float2(H2(u0.x)), f1 = __half22float2(H2(u0.y));
        float2 f2 = __half22float2(H2(u0.z)), f3 = __half22float2(H2(u0.w));
        a0.x += f0.x; a0.y += f0.y; a1.x += f1.x; a1.y += f1.y;
        a2.x += f2.x; a2.y += f2.y; a3.x += f3.x; a3.y += f3.y;
    }
#undef TREE8
#undef TREE4
#undef H2

    if (layer == 1 && sub == 0) g_cnt[node] = 0;   // clean for next replay

    const float4* b4 = reinterpret_cast<const float4*>(b);
    float4 bA = b4[sub * 2], bB = b4[sub * 2 + 1];
    float vA0 = fmaxf(a0.x * di + bA.x, 0.f);
    float vA1 = fmaxf(a0.y * di + bA.y, 0.f);
    float vA2 = fmaxf(a1.x * di + bA.z, 0.f);
    float vA3 = fmaxf(a1.y * di + bA.w, 0.f);
    float vB0 = fmaxf(a2.x * di + bB.x, 0.f);
    float vB1 = fmaxf(a2.y * di + bB.y, 0.f);
    float vB2 = fmaxf(a3.x * di + bB.z, 0.f);
    float vB3 = fmaxf(a3.y * di + bB.w, 0.f);

    if (layer == 0) {
        __half2 h0 = __floats2half2_rn(vA0, vA1);
        __half2 h1 = __floats2half2_rn(vA2, vA3);
        __half2 h2 = __floats2half2_rn(vB0, vB1);
        __half2 h3 = __floats2half2_rn(vB2, vB3);
        uint4 pk;
        pk.x = *reinterpret_cast<unsigned*>(&h0);
        pk.y = *reinterpret_cast<unsigned*>(&h1);
        pk.z = *reinterpret_cast<unsigned*>(&h2);
        pk.w = *reinterpret_cast<unsigned*>(&h3);
        reinterpret_cast<uint4*>(g_h1h + (size_t)node * DD)[sub] = pk;
    } else {
        float4* op = reinterpret_cast<float4*>(dout + (size_t)node * DD + sub * 8);
        op[0] = make_float4(vA0, vA1, vA2, vA3);
        op[1] = make_float4(vB0, vB1, vB2, vB3);
    }
}

// ---------------- launch (ONLY kernel launches — nothing else) ----------------
extern "C" void kernel_launch(void* const* d_in, const int* in_sizes, int n_in,
                              void* d_out, int out_size) {
    const float* emb = (const float*)d_in[0];
    const int*   ei  = (const int*)d_in[1];     // int32 (JAX x64 disabled)
    const float* W1  = (const float*)d_in[2];
    const float* b1  = (const float*)d_in[3];
    const float* W2  = (const float*)d_in[4];
    const float* b2  = (const float*)d_in[5];
    float*       out = (float*)d_out;

    int N = in_sizes[0] / DD;
    int E = in_sizes[1] / 2;
    const int* srcp = ei;       // edge_index[0]
    const int* dstp = ei + E;   // edge_index[1]
    int e4 = E / 4;             // int4 quads
    int gblocks = (N + 127) / 128;

    // preprocessing: single-pass bucket scatter (counts final before gemm1)
    k_scatter<<<(e4 + 255) / 256, 256>>>(srcp, dstp, e4, N);

    // layer 1
    k_gemm<<<gblocks, 256>>>(emb, W1, 0, N);
    k_agg<<<(N * 8 + 255) / 256, 256>>>(b1, out, 0, N);
    // layer 2  (launch #4 -> profiled: expect occ>=30%, dur<=10us)
    k_gemm<<<gblocks, 256>>>(emb, W2, 1, N);
    k_agg<<<(N * 8 + 255) / 256, 256>>>(b2, out, 1, N);
}

// round 16
// speedup vs baseline: 1.3454x; 1.3454x over previous
#include <cuda_runtime.h>
#include <cuda_fp16.h>
#include <cstdint>

// Problem constants (fixed by the dataset)
#define NN 100000
#define NE 1600000
#define DD 64
#define CAP 64          // bucket capacity per node (Poisson(16): P(deg>64)~2e-22)

#define XS_STRIDE 72    // halves; 144B rows: 16B-aligned + conflict-free ldmatrix

// ---------------- device scratch (no allocations allowed) ----------------
// g_cnt relies on BSS zero-init; agg layer-2 re-zeroes it (replay invariant).
__device__ __align__(256) int     g_cnt[NN];
__device__ __align__(256) int     g_bkt[(size_t)NN * CAP];   // bucket CSR
__device__ __align__(256) __half2 g_hn[(size_t)NN * 32];     // (x@W)*dinv, fp16
__device__ __align__(256) __half  g_h1h[(size_t)NN * DD];    // layer-1 out, fp16

// ------------- standalone bucket scatter: 4 edges/thread via int4 -----------
__global__ void k_scatter(const int* __restrict__ src,
                          const int* __restrict__ dst, int e4, int n) {
    int i = blockIdx.x * blockDim.x + threadIdx.x;
    if (i >= e4) return;
    int4 s4 = reinterpret_cast<const int4*>(src)[i];
    int4 d4 = reinterpret_cast<const int4*>(dst)[i];
    int dd[4] = {d4.x, d4.y, d4.z, d4.w};
    int ss[4] = {s4.x, s4.y, s4.z, s4.w};
#pragma unroll
    for (int q = 0; q < 4; q++) {
        if ((unsigned)dd[q] >= (unsigned)n || (unsigned)ss[q] >= (unsigned)n) continue;
        int slot = atomicAdd(&g_cnt[dd[q]], 1);
        if (slot < CAP) g_bkt[(size_t)dd[q] * CAP + slot] = ss[q];
    }
}

// -------- GEMM: g_hn[row] = fp16((x@W) * rsqrt(cnt[row]+1)) -----------------
// R14-proven shape: 256 rows/block (per-block W staging amortized over 2x the
// rows — R15's 128-row split doubled fixed cost and regressed 54%).
__global__ void __launch_bounds__(256) k_gemm(
    const float* __restrict__ emb, const float* __restrict__ W,
    int layer, int n) {
    __shared__ __half xs[256 * XS_STRIDE];       // 36864 B
    __shared__ __half wt[64 * XS_STRIDE];        //  9216 B  (wt[n][k])
    int tid = threadIdx.x;
    int base = blockIdx.x * 256;

    // ---- stage x rows -> fp16 shared ----
    if (layer == 0) {
        int row = base + tid;
        const float4* xr = reinterpret_cast<const float4*>(emb + (size_t)row * DD);
        bool v = row < n;
        __half2* dstp = reinterpret_cast<__half2*>(&xs[tid * XS_STRIDE]);
#pragma unroll
        for (int kk = 0; kk < 16; kk++) {
            float4 q = v ? xr[kk] : make_float4(0.f, 0.f, 0.f, 0.f);
            dstp[kk * 2]     = __floats2half2_rn(q.x, q.y);
            dstp[kk * 2 + 1] = __floats2half2_rn(q.z, q.w);
        }
    } else {
        const uint4* inp = reinterpret_cast<const uint4*>(g_h1h);
        uint4 z = make_uint4(0, 0, 0, 0);
#pragma unroll
        for (int ii = 0; ii < 8; ii++) {
            int i = tid + 256 * ii;
            int r = i >> 3, pc = i & 7;
            int gr = base + r;
            uint4 v = (gr < n) ? inp[(size_t)gr * 8 + pc] : z;
            reinterpret_cast<uint4*>(&xs[r * XS_STRIDE])[pc] = v;
        }
    }
    // ---- stage W -> fp16 transposed shared (wt[n][k]) ----
    {
        const float4* Wp4 = reinterpret_cast<const float4*>(W);
#pragma unroll
        for (int ii = 0; ii < 4; ii++) {
            int i4 = tid + 256 * ii;             // 1024 float4 total
            float4 wv = Wp4[i4];
            int flat = i4 * 4;
            int k = flat >> 6;
            int nn = flat & 63;
            wt[(nn)     * XS_STRIDE + k] = __float2half_rn(wv.x);
            wt[(nn + 1) * XS_STRIDE + k] = __float2half_rn(wv.y);
            wt[(nn + 2) * XS_STRIDE + k] = __float2half_rn(wv.z);
            wt[(nn + 3) * XS_STRIDE + k] = __float2half_rn(wv.w);
        }
    }
    __syncthreads();

    int wid = tid >> 5, lane = tid & 31;
    int g = lane >> 2, t = lane & 3;
    uint32_t xs_u32 = (uint32_t)__cvta_generic_to_shared(xs);

    // A fragments via ldmatrix.x4
    uint32_t afr[2][4][4];
#pragma unroll
    for (int mt = 0; mt < 2; mt++) {
        int rsh = wid * 32 + mt * 16 + (lane & 15);
#pragma unroll
        for (int kc = 0; kc < 4; kc++) {
            uint32_t addr = xs_u32 + rsh * (XS_STRIDE * 2) + kc * 32 + (lane >> 4) * 16;
            asm volatile("ldmatrix.sync.aligned.m8n8.x4.shared.b16 {%0,%1,%2,%3}, [%4];"
                         : "=r"(afr[mt][kc][0]), "=r"(afr[mt][kc][1]),
                           "=r"(afr[mt][kc][2]), "=r"(afr[mt][kc][3])
                         : "r"(addr));
        }
    }

    float c[8][2][4];
#pragma unroll
    for (int nt = 0; nt < 8; nt++)
#pragma unroll
        for (int mt = 0; mt < 2; mt++)
#pragma unroll
            for (int q = 0; q < 4; q++) c[nt][mt][q] = 0.f;

#pragma unroll
    for (int nt = 0; nt < 8; nt++) {
        uint32_t b0[4], b1[4];
        int nrow = nt * 8 + g;
#pragma unroll
        for (int kc = 0; kc < 4; kc++) {
            b0[kc] = *reinterpret_cast<const uint32_t*>(&wt[nrow * XS_STRIDE + kc * 16 + 2 * t]);
            b1[kc] = *reinterpret_cast<const uint32_t*>(&wt[nrow * XS_STRIDE + kc * 16 + 8 + 2 * t]);
        }
#pragma unroll
        for (int mt = 0; mt < 2; mt++) {
#pragma unroll
            for (int kc = 0; kc < 4; kc++) {
                asm volatile(
                    "mma.sync.aligned.m16n8k16.row.col.f32.f16.f16.f32 "
                    "{%0,%1,%2,%3}, {%4,%5,%6,%7}, {%8,%9}, {%0,%1,%2,%3};"
                    : "+f"(c[nt][mt][0]), "+f"(c[nt][mt][1]),
                      "+f"(c[nt][mt][2]), "+f"(c[nt][mt][3])
                    : "r"(afr[mt][kc][0]), "r"(afr[mt][kc][1]),
                      "r"(afr[mt][kc][2]), "r"(afr[mt][kc][3]),
                      "r"(b0[kc]), "r"(b1[kc]));
            }
        }
    }
    __syncthreads();   // xs reuse

    // ---- epilogue: scale by dinv, frags -> shared (conflict-free) ----
#pragma unroll
    for (int mt = 0; mt < 2; mt++) {
        int rl = wid * 32 + mt * 16 + g;
        int r0 = base + rl, r1 = r0 + 8;
        float di0 = (r0 < n) ? rsqrtf((float)(g_cnt[r0] + 1)) : 0.f;
        float di1 = (r1 < n) ? rsqrtf((float)(g_cnt[r1] + 1)) : 0.f;
#pragma unroll
        for (int nt = 0; nt < 8; nt++) {
            int col = nt * 8 + 2 * t;
            *reinterpret_cast<__half2*>(&xs[rl * XS_STRIDE + col]) =
                __floats2half2_rn(c[nt][mt][0] * di0, c[nt][mt][1] * di0);
            *reinterpret_cast<__half2*>(&xs[(rl + 8) * XS_STRIDE + col]) =
                __floats2half2_rn(c[nt][mt][2] * di1, c[nt][mt][3] * di1);
        }
    }
    __syncthreads();

    // ---- shared -> global, fully coalesced STG.128 ----
    uint4* outp = reinterpret_cast<uint4*>(g_hn) + (size_t)base * 8;
    int limit = (min(256, n - base)) * 8;
#pragma unroll
    for (int ii = 0; ii < 8; ii++) {
        int i = tid + 256 * ii;
        if (i < limit) {
            int r = i >> 3, pc = i & 7;
            outp[i] = reinterpret_cast<uint4*>(&xs[r * XS_STRIDE])[pc];
        }
    }
}

// ---- aggregation: out = relu(dinv_d*(hn_d + sum_s hn_s) + b) ---------------
// 8 lanes/node (4 nodes/warp). 8-wide fp16 HADD2 tree per iteration (8 gathers
// in flight, 28 HADD2 + one fp32 drain per 8 edges).
__global__ void __launch_bounds__(256) k_agg(
    const float* __restrict__ b, float* __restrict__ dout,
    int layer, int n) {
    int tid = blockIdx.x * blockDim.x + threadIdx.x;
    int node = tid >> 3;
    int sub = tid & 7;                 // owns half2[4*sub .. 4*sub+3]
    if (node >= n) return;
    const uint4* hn4 = reinterpret_cast<const uint4*>(g_hn);

    int cnt = g_cnt[node];
    float di = rsqrtf((float)(cnt + 1));
    int len = min(cnt, CAP);
    const int4* bp = reinterpret_cast<const int4*>(g_bkt) + (unsigned)(node * (CAP / 4));

    uint4 uself = hn4[(unsigned)(node * 8 + sub)];
    float2 a0 = __half22float2(*reinterpret_cast<__half2*>(&uself.x));
    float2 a1 = __half22float2(*reinterpret_cast<__half2*>(&uself.y));
    float2 a2 = __half22float2(*reinterpret_cast<__half2*>(&uself.z));
    float2 a3 = __half22float2(*reinterpret_cast<__half2*>(&uself.w));

#define H2(v) (*reinterpret_cast<const __half2*>(&(v)))
#define TREE8(C, ACC)                                                       \
    {                                                                       \
        __half2 s0 = __hadd2(H2(u0.C), H2(u1.C));                           \
        __half2 s1 = __hadd2(H2(u2.C), H2(u3.C));                           \
        __half2 s2 = __hadd2(H2(u4.C), H2(u5.C));                           \
        __half2 s3 = __hadd2(H2(u6.C), H2(u7.C));                           \
        float2 f = __half22float2(__hadd2(__hadd2(s0, s1), __hadd2(s2, s3)));\
        ACC.x += f.x; ACC.y += f.y;                                         \
    }
#define TREE4(C, ACC)                                                       \
    {                                                                       \
        __half2 s0 = __hadd2(H2(u0.C), H2(u1.C));                           \
        __half2 s1 = __hadd2(H2(u2.C), H2(u3.C));                           \
        float2 f = __half22float2(__hadd2(s0, s1));                         \
        ACC.x += f.x; ACC.y += f.y;                                         \
    }

    int p = 0;
    for (; p + 8 <= len; p += 8) {
        int4 e0 = bp[p >> 2];                     // broadcast across 8 lanes
        int4 e1 = bp[(p >> 2) + 1];
        uint4 u0 = hn4[(unsigned)(e0.x * 8 + sub)];
        uint4 u1 = hn4[(unsigned)(e0.y * 8 + sub)];
        uint4 u2 = hn4[(unsigned)(e0.z * 8 + sub)];
        uint4 u3 = hn4[(unsigned)(e0.w * 8 + sub)];
        uint4 u4 = hn4[(unsigned)(e1.x * 8 + sub)];
        uint4 u5 = hn4[(unsigned)(e1.y * 8 + sub)];
        uint4 u6 = hn4[(unsigned)(e1.z * 8 + sub)];
        uint4 u7 = hn4[(unsigned)(e1.w * 8 + sub)];
        TREE8(x, a0) TREE8(y, a1) TREE8(z, a2) TREE8(w, a3)
    }
    if (p + 4 <= len) {
        int4 e0 = bp[p >> 2];
        uint4 u0 = hn4[(unsigned)(e0.x * 8 + sub)];
        uint4 u1 = hn4[(unsigned)(e0.y * 8 + sub)];
        uint4 u2 = hn4[(unsigned)(e0.z * 8 + sub)];
        uint4 u3 = hn4[(unsigned)(e0.w * 8 + sub)];
        TREE4(x, a0) TREE4(y, a1) TREE4(z, a2) TREE4(w, a3)
        p += 4;
    }
    for (; p < len; p++) {
        int s = g_bkt[(unsigned)(node * CAP + p)];
        uint4 u0 = hn4[(unsigned)(s * 8 + sub)];
        float2 f0 = __half22float2(H2(u0.x)), f1 = __half22float2(H2(u0.y));
        float2 f2 = __half22float2(H2(u0.z)), f3 = __half22float2(H2(u0.w));
        a0.x += f0.x; a0.y += f0.y; a1.x += f1.x; a1.y += f1.y;
        a2.x += f2.x; a2.y += f2.y; a3.x += f3.x; a3.y += f3.y;
    }
#undef TREE8
#undef TREE4
#undef H2

    if (layer == 1 && sub == 0) g_cnt[node] = 0;   // clean for next replay

    const float4* b4 = reinterpret_cast<const float4*>(b);
    float4 bA = b4[sub * 2], bB = b4[sub * 2 + 1];
    float vA0 = fmaxf(a0.x * di + bA.x, 0.f);
    float vA1 = fmaxf(a0.y * di + bA.y, 0.f);
    float vA2 = fmaxf(a1.x * di + bA.z, 0.f);
    float vA3 = fmaxf(a1.y * di + bA.w, 0.f);
    float vB0 = fmaxf(a2.x * di + bB.x, 0.f);
    float vB1 = fmaxf(a2.y * di + bB.y, 0.f);
    float vB2 = fmaxf(a3.x * di + bB.z, 0.f);
    float vB3 = fmaxf(a3.y * di + bB.w, 0.f);

    if (layer == 0) {
        __half2 h0 = __floats2half2_rn(vA0, vA1);
        __half2 h1 = __floats2half2_rn(vA2, vA3);
        __half2 h2 = __floats2half2_rn(vB0, vB1);
        __half2 h3 = __floats2half2_rn(vB2, vB3);
        uint4 pk;
        pk.x = *reinterpret_cast<unsigned*>(&h0);
        pk.y = *reinterpret_cast<unsigned*>(&h1);
        pk.z = *reinterpret_cast<unsigned*>(&h2);
        pk.w = *reinterpret_cast<unsigned*>(&h3);
        reinterpret_cast<uint4*>(g_h1h + (size_t)node * DD)[sub] = pk;
    } else {
        float4* op = reinterpret_cast<float4*>(dout + (size_t)node * DD + sub * 8);
        op[0] = make_float4(vA0, vA1, vA2, vA3);
        op[1] = make_float4(vB0, vB1, vB2, vB3);
    }
}

// ---------------- launch (ONLY kernel launches — nothing else) ----------------
extern "C" void kernel_launch(void* const* d_in, const int* in_sizes, int n_in,
                              void* d_out, int out_size) {
    const float* emb = (const float*)d_in[0];
    const int*   ei  = (const int*)d_in[1];     // int32 (JAX x64 disabled)
    const float* W1  = (const float*)d_in[2];
    const float* b1  = (const float*)d_in[3];
    const float* W2  = (const float*)d_in[4];
    const float* b2  = (const float*)d_in[5];
    float*       out = (float*)d_out;

    int N = in_sizes[0] / DD;
    int E = in_sizes[1] / 2;
    const int* srcp = ei;       // edge_index[0]
    const int* dstp = ei + E;   // edge_index[1]
    int e4 = E / 4;             // int4 quads
    int gblocks = (N + 255) / 256;

    // preprocessing: single-pass bucket scatter (counts final before gemm1)
    k_scatter<<<(e4 + 255) / 256, 256>>>(srcp, dstp, e4, N);

    // layer 1
    k_gemm<<<gblocks, 256>>>(emb, W1, 0, N);
    k_agg<<<(N * 8 + 255) / 256, 256>>>(b1, out, 0, N);
    // layer 2  (launch #4 -> profiled: control, expect ~12.9us)
    k_gemm<<<gblocks, 256>>>(emb, W2, 1, N);
    k_agg<<<(N * 8 + 255) / 256, 256>>>(b2, out, 1, N);
}

// round 17
// speedup vs baseline: 1.5034x; 1.1175x over previous
#include <cuda_runtime.h>
#include <cuda_fp16.h>
#include <cstdint>

// Problem constants (fixed by the dataset)
#define NN 100000
#define NE 1600000
#define DD 64
#define CAP 64          // bucket capacity per node (Poisson(16): P(deg>64)~2e-22)

#define XS_STRIDE 72    // halves; 144B rows: 16B-aligned + conflict-free ldmatrix

// ---------------- device scratch (no allocations allowed) ----------------
// g_cnt relies on BSS zero-init; agg layer-2 re-zeroes it (replay invariant).
__device__ __align__(256) int     g_cnt[NN];
__device__ __align__(256) int     g_bkt[(size_t)NN * CAP];   // bucket CSR
__device__ __align__(256) __half2 g_hn[(size_t)NN * 32];     // (x@W)*dinv, fp16
__device__ __align__(256) __half  g_h1h[(size_t)NN * DD];    // layer-1 out, fp16

// ------------- standalone bucket scatter: 4 edges/thread via int4 -----------
__global__ void k_scatter(const int* __restrict__ src,
                          const int* __restrict__ dst, int e4, int n) {
    int i = blockIdx.x * blockDim.x + threadIdx.x;
    if (i >= e4) return;
    int4 s4 = reinterpret_cast<const int4*>(src)[i];
    int4 d4 = reinterpret_cast<const int4*>(dst)[i];
    int dd[4] = {d4.x, d4.y, d4.z, d4.w};
    int ss[4] = {s4.x, s4.y, s4.z, s4.w};
#pragma unroll
    for (int q = 0; q < 4; q++) {
        if ((unsigned)dd[q] >= (unsigned)n || (unsigned)ss[q] >= (unsigned)n) continue;
        int slot = atomicAdd(&g_cnt[dd[q]], 1);
        if (slot < CAP) g_bkt[(size_t)dd[q] * CAP + slot] = ss[q];
    }
}

// -------- GEMM: g_hn[row] = fp16((x@W) * rsqrt(cnt[row]+1)) -----------------
// 256 rows/block (R14-proven). W staged K-MAJOR (natural layout, conflict-free
// 8B stores); B fragments via ldmatrix.x4.trans (replaces 64 conflicted
// LDS.32/thread + 16 scalar transposed STS/thread that drove L1 to 31%).
__global__ void __launch_bounds__(256) k_gemm(
    const float* __restrict__ emb, const float* __restrict__ W,
    int layer, int n) {
    __shared__ __half xs[256 * XS_STRIDE];       // 36864 B
    __shared__ __half wt[64 * XS_STRIDE];        //  9216 B  (wt[k][n], k-major)
    int tid = threadIdx.x;
    int base = blockIdx.x * 256;

    // ---- stage x rows -> fp16 shared (cooperative, coalesced) ----
    if (layer == 0) {
        const float4* xr = reinterpret_cast<const float4*>(emb);
#pragma unroll
        for (int ii = 0; ii < 16; ii++) {
            int i = tid + 256 * ii;              // 0..4095 (256 rows x 16 f4)
            int r = i >> 4, kk = i & 15;
            int gr = base + r;
            float4 q = (gr < n) ? xr[(size_t)gr * 16 + kk]
                                : make_float4(0.f, 0.f, 0.f, 0.f);
            __half2* dp = reinterpret_cast<__half2*>(&xs[r * XS_STRIDE + kk * 4]);
            dp[0] = __floats2half2_rn(q.x, q.y);
            dp[1] = __floats2half2_rn(q.z, q.w);
        }
    } else {
        const uint4* inp = reinterpret_cast<const uint4*>(g_h1h);
        uint4 z = make_uint4(0, 0, 0, 0);
#pragma unroll
        for (int ii = 0; ii < 8; ii++) {
            int i = tid + 256 * ii;
            int r = i >> 3, pc = i & 7;
            int gr = base + r;
            uint4 v = (gr < n) ? inp[(size_t)gr * 8 + pc] : z;
            reinterpret_cast<uint4*>(&xs[r * XS_STRIDE])[pc] = v;
        }
    }
    // ---- stage W -> fp16 K-MAJOR shared wt[k][n] (conflict-free 8B stores) --
    {
        const float4* Wp4 = reinterpret_cast<const float4*>(W);
#pragma unroll
        for (int ii = 0; ii < 4; ii++) {
            int i4 = tid + 256 * ii;             // 1024 float4 total
            float4 wv = Wp4[i4];
            int flat = i4 * 4;
            int k = flat >> 6;
            int nn = flat & 63;                  // multiple of 4 -> 8B aligned
            __half2 ha = __floats2half2_rn(wv.x, wv.y);
            __half2 hb = __floats2half2_rn(wv.z, wv.w);
            uint2 pk;
            pk.x = *reinterpret_cast<unsigned*>(&ha);
            pk.y = *reinterpret_cast<unsigned*>(&hb);
            *reinterpret_cast<uint2*>(&wt[k * XS_STRIDE + nn]) = pk;
        }
    }
    __syncthreads();

    int wid = tid >> 5, lane = tid & 31;
    int g = lane >> 2, t = lane & 3;
    uint32_t xs_u32 = (uint32_t)__cvta_generic_to_shared(xs);
    uint32_t wt_u32 = (uint32_t)__cvta_generic_to_shared(wt);

    // A fragments via ldmatrix.x4
    uint32_t afr[2][4][4];
#pragma unroll
    for (int mt = 0; mt < 2; mt++) {
        int rsh = wid * 32 + mt * 16 + (lane & 15);
#pragma unroll
        for (int kc = 0; kc < 4; kc++) {
            uint32_t addr = xs_u32 + rsh * (XS_STRIDE * 2) + kc * 32 + (lane >> 4) * 16;
            asm volatile("ldmatrix.sync.aligned.m8n8.x4.shared.b16 {%0,%1,%2,%3}, [%4];"
                         : "=r"(afr[mt][kc][0]), "=r"(afr[mt][kc][1]),
                           "=r"(afr[mt][kc][2]), "=r"(afr[mt][kc][3])
                         : "r"(addr));
        }
    }

    float c[8][2][4];
#pragma unroll
    for (int nt = 0; nt < 8; nt++)
#pragma unroll
        for (int mt = 0; mt < 2; mt++)
#pragma unroll
            for (int q = 0; q < 4; q++) c[nt][mt][q] = 0.f;

#pragma unroll
    for (int nt = 0; nt < 8; nt++) {
        // B frags: 2x ldmatrix.x4.trans from k-major wt; lane l -> k-row l.
        // regs: {b0[kc0], b1[kc0], b0[kc1], b1[kc1]} per x4 (k-groups of 8).
        uint32_t bb[8];
        uint32_t baddr0 = wt_u32 + (lane * XS_STRIDE + nt * 8) * 2;          // k 0..31
        uint32_t baddr1 = baddr0 + 32 * XS_STRIDE * 2;                       // k 32..63
        asm volatile("ldmatrix.sync.aligned.m8n8.x4.trans.shared.b16 {%0,%1,%2,%3}, [%4];"
                     : "=r"(bb[0]), "=r"(bb[1]), "=r"(bb[2]), "=r"(bb[3])
                     : "r"(baddr0));
        asm volatile("ldmatrix.sync.aligned.m8n8.x4.trans.shared.b16 {%0,%1,%2,%3}, [%4];"
                     : "=r"(bb[4]), "=r"(bb[5]), "=r"(bb[6]), "=r"(bb[7])
                     : "r"(baddr1));
#pragma unroll
        for (int mt = 0; mt < 2; mt++) {
#pragma unroll
            for (int kc = 0; kc < 4; kc++) {
                asm volatile(
                    "mma.sync.aligned.m16n8k16.row.col.f32.f16.f16.f32 "
                    "{%0,%1,%2,%3}, {%4,%5,%6,%7}, {%8,%9}, {%0,%1,%2,%3};"
                    : "+f"(c[nt][mt][0]), "+f"(c[nt][mt][1]),
                      "+f"(c[nt][mt][2]), "+f"(c[nt][mt][3])
                    : "r"(afr[mt][kc][0]), "r"(afr[mt][kc][1]),
                      "r"(afr[mt][kc][2]), "r"(afr[mt][kc][3]),
                      "r"(bb[kc * 2]), "r"(bb[kc * 2 + 1]));
            }
        }
    }
    __syncthreads();   // xs reuse

    // ---- epilogue: scale by dinv, frags -> shared (conflict-free) ----
#pragma unroll
    for (int mt = 0; mt < 2; mt++) {
        int rl = wid * 32 + mt * 16 + g;
        int r0 = base + rl, r1 = r0 + 8;
        float di0 = (r0 < n) ? rsqrtf((float)(g_cnt[r0] + 1)) : 0.f;
        float di1 = (r1 < n) ? rsqrtf((float)(g_cnt[r1] + 1)) : 0.f;
#pragma unroll
        for (int nt = 0; nt < 8; nt++) {
            int col = nt * 8 + 2 * t;
            *reinterpret_cast<__half2*>(&xs[rl * XS_STRIDE + col]) =
                __floats2half2_rn(c[nt][mt][0] * di0, c[nt][mt][1] * di0);
            *reinterpret_cast<__half2*>(&xs[(rl + 8) * XS_STRIDE + col]) =
                __floats2half2_rn(c[nt][mt][2] * di1, c[nt][mt][3] * di1);
        }
    }
    __syncthreads();

    // ---- shared -> global, fully coalesced STG.128 ----
    uint4* outp = reinterpret_cast<uint4*>(g_hn) + (size_t)base * 8;
    int limit = (min(256, n - base)) * 8;
#pragma unroll
    for (int ii = 0; ii < 8; ii++) {
        int i = tid + 256 * ii;
        if (i < limit) {
            int r = i >> 3, pc = i & 7;
            outp[i] = reinterpret_cast<uint4*>(&xs[r * XS_STRIDE])[pc];
        }
    }
}

// ---- aggregation (R14-proven 4-wide HADD2 tree): -----------------------
// out = relu(dinv_d*(hn_d + sum_s hn_s) + b); 8 lanes/node, uint4 gathers.
__global__ void __launch_bounds__(256) k_agg(
    const float* __restrict__ b, float* __restrict__ dout,
    int layer, int n) {
    int tid = blockIdx.x * blockDim.x + threadIdx.x;
    int node = tid >> 3;
    int sub = tid & 7;                 // owns half2[4*sub .. 4*sub+3]
    if (node >= n) return;
    const uint4* hn4 = reinterpret_cast<const uint4*>(g_hn);

    int cnt = g_cnt[node];
    float di = rsqrtf((float)(cnt + 1));
    int len = min(cnt, CAP);
    const int4* bp = reinterpret_cast<const int4*>(g_bkt) + (unsigned)(node * (CAP / 4));

    uint4 uself = hn4[(unsigned)(node * 8 + sub)];
    float2 a0 = __half22float2(*reinterpret_cast<__half2*>(&uself.x));
    float2 a1 = __half22float2(*reinterpret_cast<__half2*>(&uself.y));
    float2 a2 = __half22float2(*reinterpret_cast<__half2*>(&uself.z));
    float2 a3 = __half22float2(*reinterpret_cast<__half2*>(&uself.w));

#define H2(v) (*reinterpret_cast<const __half2*>(&(v)))
    int p = 0;
    for (; p + 4 <= len; p += 4) {
        int4 e = bp[p >> 2];                      // broadcast across 8 lanes
        uint4 u0 = hn4[(unsigned)(e.x * 8 + sub)];
        uint4 u1 = hn4[(unsigned)(e.y * 8 + sub)];
        uint4 u2 = hn4[(unsigned)(e.z * 8 + sub)];
        uint4 u3 = hn4[(unsigned)(e.w * 8 + sub)];
        __half2 t0 = __hadd2(__hadd2(H2(u0.x), H2(u1.x)), __hadd2(H2(u2.x), H2(u3.x)));
        __half2 t1 = __hadd2(__hadd2(H2(u0.y), H2(u1.y)), __hadd2(H2(u2.y), H2(u3.y)));
        __half2 t2 = __hadd2(__hadd2(H2(u0.z), H2(u1.z)), __hadd2(H2(u2.z), H2(u3.z)));
        __half2 t3 = __hadd2(__hadd2(H2(u0.w), H2(u1.w)), __hadd2(H2(u2.w), H2(u3.w)));
        float2 f0 = __half22float2(t0), f1 = __half22float2(t1);
        float2 f2 = __half22float2(t2), f3 = __half22float2(t3);
        a0.x += f0.x; a0.y += f0.y; a1.x += f1.x; a1.y += f1.y;
        a2.x += f2.x; a2.y += f2.y; a3.x += f3.x; a3.y += f3.y;
    }
    for (; p < len; p++) {
        int s = g_bkt[(unsigned)(node * CAP + p)];
        uint4 u0 = hn4[(unsigned)(s * 8 + sub)];
        float2 f0 = __half22float2(H2(u0.x)), f1 = __half22float2(H2(u0.y));
        float2 f2 = __half22float2(H2(u0.z)), f3 = __half22float2(H2(u0.w));
        a0.x += f0.x; a0.y += f0.y; a1.x += f1.x; a1.y += f1.y;
        a2.x += f2.x; a2.y += f2.y; a3.x += f3.x; a3.y += f3.y;
    }
#undef H2

    if (layer == 1 && sub == 0) g_cnt[node] = 0;   // clean for next replay

    const float4* b4 = reinterpret_cast<const float4*>(b);
    float4 bA = b4[sub * 2], bB = b4[sub * 2 + 1];
    float vA0 = fmaxf(a0.x * di + bA.x, 0.f);
    float vA1 = fmaxf(a0.y * di + bA.y, 0.f);
    float vA2 = fmaxf(a1.x * di + bA.z, 0.f);
    float vA3 = fmaxf(a1.y * di + bA.w, 0.f);
    float vB0 = fmaxf(a2.x * di + bB.x, 0.f);
    float vB1 = fmaxf(a2.y * di + bB.y, 0.f);
    float vB2 = fmaxf(a3.x * di + bB.z, 0.f);
    float vB3 = fmaxf(a3.y * di + bB.w, 0.f);

    if (layer == 0) {
        __half2 h0 = __floats2half2_rn(vA0, vA1);
        __half2 h1 = __floats2half2_rn(vA2, vA3);
        __half2 h2 = __floats2half2_rn(vB0, vB1);
        __half2 h3 = __floats2half2_rn(vB2, vB3);
        uint4 pk;
        pk.x = *reinterpret_cast<unsigned*>(&h0);
        pk.y = *reinterpret_cast<unsigned*>(&h1);
        pk.z = *reinterpret_cast<unsigned*>(&h2);
        pk.w = *reinterpret_cast<unsigned*>(&h3);
        reinterpret_cast<uint4*>(g_h1h + (size_t)node * DD)[sub] = pk;
    } else {
        float4* op = reinterpret_cast<float4*>(dout + (size_t)node * DD + sub * 8);
        op[0] = make_float4(vA0, vA1, vA2, vA3);
        op[1] = make_float4(vB0, vB1, vB2, vB3);
    }
}

// ---------------- launch (ONLY kernel launches — nothing else) ----------------
extern "C" void kernel_launch(void* const* d_in, const int* in_sizes, int n_in,
                              void* d_out, int out_size) {
    const float* emb = (const float*)d_in[0];
    const int*   ei  = (const int*)d_in[1];     // int32 (JAX x64 disabled)
    const float* W1  = (const float*)d_in[2];
    const float* b1  = (const float*)d_in[3];
    const float* W2  = (const float*)d_in[4];
    const float* b2  = (const float*)d_in[5];
    float*       out = (float*)d_out;

    int N = in_sizes[0] / DD;
    int E = in_sizes[1] / 2;
    const int* srcp = ei;       // edge_index[0]
    const int* dstp = ei + E;   // edge_index[1]
    int e4 = E / 4;             // int4 quads
    int gblocks = (N + 255) / 256;

    // preprocessing: single-pass bucket scatter (counts final before gemm1)
    k_scatter<<<(e4 + 255) / 256, 256>>>(srcp, dstp, e4, N);

    // layer 1
    k_gemm<<<gblocks, 256>>>(emb, W1, 0, N);
    k_agg<<<(N * 8 + 255) / 256, 256>>>(b1, out, 0, N);
    // layer 2  (launch #4 -> profiled: expect <=11.5us, L1 <= 25%)
    k_gemm<<<gblocks, 256>>>(emb, W2, 1, N);
    k_agg<<<(N * 8 + 255) / 256, 256>>>(b2, out, 1, N);
}